// round 1
// baseline (speedup 1.0000x reference)
#include <cuda_runtime.h>

#define N_BATCH 4
#define C_TOTAL 2048
#define T_FR    8
#define HH      16
#define WW      16
#define R_ROIS  32
#define OUT_SZ  16
#define SCALE   (1.0f/16.0f)

#define C_CHUNKS 16
#define C_PER    (C_TOTAL / C_CHUNKS)   // 128

#define OUT_ELEMS   (R_ROIS * C_TOTAL * OUT_SZ * OUT_SZ)   // 16777216
#define FEATP_ELEMS (N_BATCH * C_TOTAL * HH * WW)          // 2097152

// ---------------------------------------------------------------------------
// Kernel 1: temporal mean over T=8.  feat [N,C,T,16,16] -> feat_p [N,C,16,16]
// float4 vectorized; fully coalesced reads/writes.
// ---------------------------------------------------------------------------
__global__ void tmean_kernel(const float* __restrict__ feat,
                             float* __restrict__ featp) {
    int idx = blockIdx.x * blockDim.x + threadIdx.x;   // float4 index
    const int TOTAL4 = (N_BATCH * C_TOTAL * HH * WW) / 4;  // 524288
    if (idx >= TOTAL4) return;
    const float4* f4 = (const float4*)feat;
    int pix = idx & 63;          // float4 within one 16x16 plane (64 per plane)
    int nc  = idx >> 6;          // (n*C + c)
    long base = (long)nc * (T_FR * 64) + pix;
    float4 a = f4[base];
    #pragma unroll
    for (int t = 1; t < T_FR; t++) {
        float4 v = f4[base + (long)t * 64];
        a.x += v.x; a.y += v.y; a.z += v.z; a.w += v.w;
    }
    a.x *= 0.125f; a.y *= 0.125f; a.z *= 0.125f; a.w *= 0.125f;
    ((float4*)featp)[idx] = a;
}

// ---------------------------------------------------------------------------
// Kernel 2: aligned RoIAlign (avg pool, ratio=2) on feat_p.
// Block = (channel chunk, roi). 256 threads = one output pixel each.
// Per channel: stage the 1KB 16x16 plane in shared (coalesced), then each
// thread does a separable 4x4 weighted gather from shared.
// Geometry (indices + weights, masks folded in) lives in registers.
// ---------------------------------------------------------------------------
__global__ __launch_bounds__(256) void roialign_kernel(
        const float* __restrict__ featp,
        const float* __restrict__ rois,
        float* __restrict__ out) {
    const int r     = blockIdx.y;
    const int cbase = blockIdx.x * C_PER;
    const int tid   = threadIdx.x;
    const int px    = tid & 15;
    const int py    = tid >> 4;

    // --- geometry, computed once per thread ---
    const float r0 = rois[r * 5 + 0];
    const float bx1 = rois[r * 5 + 1] * SCALE - 0.5f;
    const float by1 = rois[r * 5 + 2] * SCALE - 0.5f;
    const float bx2 = rois[r * 5 + 3] * SCALE - 0.5f;
    const float by2 = rois[r * 5 + 4] * SCALE - 0.5f;
    const int nb = (int)r0;
    const float bin_h = (by2 - by1) * (1.0f / OUT_SZ);
    const float bin_w = (bx2 - bx1) * (1.0f / OUT_SZ);

    int   YO[4]; float WY[4];   // YO = row*16 precomputed
    int   XI[4]; float WX[4];

    #pragma unroll
    for (int s = 0; s < 2; s++) {
        // y axis
        {
            float g  = ((float)(2 * py + s) + 0.5f) * 0.5f;
            float ys = by1 + g * bin_h;
            float vm = (ys >= -1.0f && ys <= (float)HH) ? 0.5f : 0.0f; // mask * 1/2
            float y  = fminf(fmaxf(ys, 0.0f), (float)(HH - 1));
            float y0f = floorf(y);
            int   y0  = (int)y0f;
            int   y1  = min(y0 + 1, HH - 1);
            float ly  = y - y0f;
            float hy  = 1.0f - ly;
            YO[2 * s]     = y0 * WW;  WY[2 * s]     = hy * vm;
            YO[2 * s + 1] = y1 * WW;  WY[2 * s + 1] = ly * vm;
        }
        // x axis
        {
            float g  = ((float)(2 * px + s) + 0.5f) * 0.5f;
            float xs = bx1 + g * bin_w;
            float vm = (xs >= -1.0f && xs <= (float)WW) ? 0.5f : 0.0f;
            float x  = fminf(fmaxf(xs, 0.0f), (float)(WW - 1));
            float x0f = floorf(x);
            int   x0  = (int)x0f;
            int   x1  = min(x0 + 1, WW - 1);
            float lx  = x - x0f;
            float hx  = 1.0f - lx;
            XI[2 * s]     = x0;  WX[2 * s]     = hx * vm;
            XI[2 * s + 1] = x1;  WX[2 * s + 1] = lx * vm;
        }
    }

    __shared__ float tile[2][HH * WW];

    const float* fp  = featp + ((long)nb * C_TOTAL + cbase) * (HH * WW) + tid;
    float*       op  = out   + ((long)r  * C_TOTAL + cbase) * (HH * WW) + tid;

    float v = fp[0];   // prefetch c = cbase
    #pragma unroll 1
    for (int i = 0; i < C_PER; i++) {
        tile[i & 1][tid] = v;
        if (i + 1 < C_PER) v = fp[(long)(i + 1) * (HH * WW)];
        __syncthreads();
        const float* t0 = tile[i & 1];
        float acc = 0.0f;
        #pragma unroll
        for (int a = 0; a < 4; a++) {
            float d = WX[0] * t0[YO[a] + XI[0]];
            d = fmaf(WX[1], t0[YO[a] + XI[1]], d);
            d = fmaf(WX[2], t0[YO[a] + XI[2]], d);
            d = fmaf(WX[3], t0[YO[a] + XI[3]], d);
            acc = fmaf(WY[a], d, acc);
        }
        op[(long)i * (HH * WW)] = acc;
        // NOTE: single sync per iteration is safe: tile[i&1] is rewritten at
        // iteration i+2, and the sync at i+1 orders compute(i) before STS(i+2).
    }
}

// ---------------------------------------------------------------------------
extern "C" void kernel_launch(void* const* d_in, const int* in_sizes, int n_in,
                              void* d_out, int out_size) {
    const float* feat = (const float*)d_in[0];
    const float* rois = (const float*)d_in[1];
    float* out   = (float*)d_out;
    float* featp = out + OUT_ELEMS;   // feat_p tensor is the 2nd tuple element

    // Kernel 1: temporal mean -> feat_p (written straight into output tail)
    {
        const int TOTAL4 = FEATP_ELEMS / 4;  // 524288
        tmean_kernel<<<(TOTAL4 + 255) / 256, 256>>>(feat, featp);
    }
    // Kernel 2: RoIAlign reading feat_p from the output buffer
    {
        dim3 grid(C_CHUNKS, R_ROIS);   // 16 x 32 = 512 blocks
        roialign_kernel<<<grid, 256>>>(featp, rois, out);
    }
}